// round 1
// baseline (speedup 1.0000x reference)
#include <cuda_runtime.h>
#include <math.h>

// Problem dims
#define Bb 8
#define Ss 1024
#define Dd 1024
#define Hh 16
#define HDIM 64
#define Ff 4096
#define Mm (Bb*Ss)   // 8192 rows

// ---------------------------------------------------------------------------
// Scratch (device globals; allocation-free per harness rules)
// ---------------------------------------------------------------------------
__device__ float g_Q[(size_t)Mm * Dd];              // Q proj -> later context
__device__ float g_K[(size_t)Mm * Dd];              // K proj -> later X (o-proj out) -> Z (ffn2 out)
__device__ float g_V[(size_t)Mm * Dd];              // V proj -> later attn_out
__device__ float g_F[(size_t)Mm * Ff];              // FFN intermediate
__device__ float g_S[(size_t)Bb * Hh * Ss * Ss];    // scores, then softmax'd P (in place)

// ---------------------------------------------------------------------------
// Generic SGEMM: C[M,N] = A[M,K] @ W[K,N] + bias[N]  (optional ReLU)
// 128x128 tile, BK=16, 256 threads, 8x8 per-thread microtile.
// All dims here are multiples of 128 so no bounds checks.
// ---------------------------------------------------------------------------
__global__ void __launch_bounds__(256) sgemm_bias(
    const float* __restrict__ A, const float* __restrict__ W,
    const float* __restrict__ bias, float* __restrict__ C,
    int M, int N, int K, int relu)
{
    __shared__ float As[16][128];   // transposed A tile: As[k][m]
    __shared__ float Ws[16][128];   // Ws[k][n]
    const int tid = threadIdx.x;
    const int tx = tid & 15;
    const int ty = tid >> 4;
    const int row0 = blockIdx.y * 128;
    const int col0 = blockIdx.x * 128;

    float acc[8][8];
#pragma unroll
    for (int i = 0; i < 8; i++)
#pragma unroll
        for (int j = 0; j < 8; j++) acc[i][j] = 0.f;

    for (int k0 = 0; k0 < K; k0 += 16) {
#pragma unroll
        for (int l = 0; l < 2; l++) {
            int slot = tid + l * 256;        // 0..511
            int r = slot >> 2;               // 0..127
            int c = (slot & 3) * 4;          // 0..12
            float4 v = *(const float4*)(A + (size_t)(row0 + r) * K + k0 + c);
            As[c + 0][r] = v.x; As[c + 1][r] = v.y;
            As[c + 2][r] = v.z; As[c + 3][r] = v.w;
        }
#pragma unroll
        for (int l = 0; l < 2; l++) {
            int slot = tid + l * 256;
            int r = slot >> 5;               // 0..15
            int c = (slot & 31) * 4;         // 0..124
            *(float4*)&Ws[r][c] = *(const float4*)(W + (size_t)(k0 + r) * N + col0 + c);
        }
        __syncthreads();
#pragma unroll
        for (int kk = 0; kk < 16; kk++) {
            float a[8], b[8];
            *(float4*)&a[0] = *(const float4*)&As[kk][ty * 8];
            *(float4*)&a[4] = *(const float4*)&As[kk][ty * 8 + 4];
            *(float4*)&b[0] = *(const float4*)&Ws[kk][tx * 8];
            *(float4*)&b[4] = *(const float4*)&Ws[kk][tx * 8 + 4];
#pragma unroll
            for (int i = 0; i < 8; i++)
#pragma unroll
                for (int j = 0; j < 8; j++) acc[i][j] += a[i] * b[j];
        }
        __syncthreads();
    }

#pragma unroll
    for (int i = 0; i < 8; i++) {
        int row = row0 + ty * 8 + i;
#pragma unroll
        for (int j = 0; j < 8; j += 4) {
            int col = col0 + tx * 8 + j;
            float4 bv = *(const float4*)(bias + col);
            float4 o;
            o.x = acc[i][j + 0] + bv.x;
            o.y = acc[i][j + 1] + bv.y;
            o.z = acc[i][j + 2] + bv.z;
            o.w = acc[i][j + 3] + bv.w;
            if (relu) {
                o.x = fmaxf(o.x, 0.f); o.y = fmaxf(o.y, 0.f);
                o.z = fmaxf(o.z, 0.f); o.w = fmaxf(o.w, 0.f);
            }
            *(float4*)(C + (size_t)row * N + col) = o;
        }
    }
}

// ---------------------------------------------------------------------------
// scores[bh, sq, sk] = (Q_h[sq,:] . K_h[sk,:]) / 8 + (1-mask[b,sk]) * -10000
// Batched over 128 (b,h); 64x64 tile per block, K = HD = 64 in one shot.
// ---------------------------------------------------------------------------
__global__ void __launch_bounds__(256) scores_kernel(
    const float* __restrict__ Q, const float* __restrict__ K,
    const float* __restrict__ mask, float* __restrict__ Sout)
{
    __shared__ float Qs[64][68];   // [d][sq], padded
    __shared__ float Ks[64][68];   // [d][sk], padded
    const int bh = blockIdx.z;
    const int b = bh >> 4;
    const int h = bh & 15;
    const int sq0 = blockIdx.y * 64;
    const int sk0 = blockIdx.x * 64;
    const float* Qb = Q + (size_t)b * Ss * Dd + (size_t)h * HDIM;
    const float* Kb = K + (size_t)b * Ss * Dd + (size_t)h * HDIM;
    const int tid = threadIdx.x;

#pragma unroll
    for (int l = 0; l < 4; l++) {
        int slot = tid + l * 256;        // 0..1023
        int r = slot >> 4;               // 0..63
        int c = (slot & 15) * 4;         // 0..60
        float4 q4 = *(const float4*)(Qb + (size_t)(sq0 + r) * Dd + c);
        Qs[c + 0][r] = q4.x; Qs[c + 1][r] = q4.y;
        Qs[c + 2][r] = q4.z; Qs[c + 3][r] = q4.w;
        float4 k4 = *(const float4*)(Kb + (size_t)(sk0 + r) * Dd + c);
        Ks[c + 0][r] = k4.x; Ks[c + 1][r] = k4.y;
        Ks[c + 2][r] = k4.z; Ks[c + 3][r] = k4.w;
    }
    __syncthreads();

    const int tx = tid & 15, ty = tid >> 4;
    float acc[4][4] = {};
#pragma unroll
    for (int d = 0; d < 64; d++) {
        float q[4], k[4];
        *(float4*)q = *(const float4*)&Qs[d][ty * 4];
        *(float4*)k = *(const float4*)&Ks[d][tx * 4];
#pragma unroll
        for (int i = 0; i < 4; i++)
#pragma unroll
            for (int j = 0; j < 4; j++) acc[i][j] += q[i] * k[j];
    }

    float* Sb = Sout + (size_t)bh * Ss * Ss;
    float4 m4 = *(const float4*)(mask + (size_t)b * Ss + sk0 + tx * 4);
    float madd[4] = { (1.0f - m4.x) * -10000.0f, (1.0f - m4.y) * -10000.0f,
                      (1.0f - m4.z) * -10000.0f, (1.0f - m4.w) * -10000.0f };
#pragma unroll
    for (int i = 0; i < 4; i++) {
        int sq = sq0 + ty * 4 + i;
        float4 o;
        o.x = acc[i][0] * 0.125f + madd[0];
        o.y = acc[i][1] * 0.125f + madd[1];
        o.z = acc[i][2] * 0.125f + madd[2];
        o.w = acc[i][3] * 0.125f + madd[3];
        *(float4*)(Sb + (size_t)sq * Ss + sk0 + tx * 4) = o;
    }
}

// ---------------------------------------------------------------------------
// Row softmax over S=1024, in place on g_S; optionally mirrored to d_out
// (attn_weights output). One block per row, 256 threads x 4 elements.
// ---------------------------------------------------------------------------
__global__ void __launch_bounds__(256) softmax_kernel(
    float* __restrict__ Sbuf, float* __restrict__ ext)
{
    __shared__ float sbuf[8];
    const size_t row = blockIdx.x;
    float* p = Sbuf + row * Ss;
    const int tid = threadIdx.x;
    const int lane = tid & 31, w = tid >> 5;

    float4 x = *(const float4*)(p + tid * 4);
    float m = fmaxf(fmaxf(x.x, x.y), fmaxf(x.z, x.w));
#pragma unroll
    for (int o = 16; o > 0; o >>= 1) m = fmaxf(m, __shfl_xor_sync(~0u, m, o));
    if (lane == 0) sbuf[w] = m;
    __syncthreads();
    m = sbuf[0];
#pragma unroll
    for (int i = 1; i < 8; i++) m = fmaxf(m, sbuf[i]);

    float4 e;
    e.x = expf(x.x - m); e.y = expf(x.y - m);
    e.z = expf(x.z - m); e.w = expf(x.w - m);
    float s = e.x + e.y + e.z + e.w;
#pragma unroll
    for (int o = 16; o > 0; o >>= 1) s += __shfl_xor_sync(~0u, s, o);
    __syncthreads();
    if (lane == 0) sbuf[w] = s;
    __syncthreads();
    s = 0.f;
#pragma unroll
    for (int i = 0; i < 8; i++) s += sbuf[i];
    float inv = 1.0f / s;
    e.x *= inv; e.y *= inv; e.z *= inv; e.w *= inv;
    *(float4*)(p + tid * 4) = e;
    if (ext) *(float4*)(ext + row * Ss + tid * 4) = e;
}

// ---------------------------------------------------------------------------
// context[b, sq, h*64 + d] = sum_sk P[bh, sq, sk] * V[b, sk, h*64 + d]
// Batched over 128 (b,h); 64(sq) x 64(d) tile per block, BK = 32.
// ---------------------------------------------------------------------------
__global__ void __launch_bounds__(256) pv_kernel(
    const float* __restrict__ P, const float* __restrict__ V,
    float* __restrict__ ctx)
{
    __shared__ float Ps[32][68];   // [sk][sq]
    __shared__ float Vs[32][68];   // [sk][d]
    const int bh = blockIdx.y;
    const int b = bh >> 4, h = bh & 15;
    const int sq0 = blockIdx.x * 64;
    const float* Pb = P + (size_t)bh * Ss * Ss;
    const float* Vb = V + (size_t)b * Ss * Dd + (size_t)h * HDIM;
    const int tid = threadIdx.x;
    const int tx = tid & 15, ty = tid >> 4;

    float acc[4][4] = {};
    for (int k0 = 0; k0 < Ss; k0 += 32) {
#pragma unroll
        for (int l = 0; l < 2; l++) {
            int slot = tid + l * 256;    // 0..511
            int r = slot >> 3;           // sq 0..63
            int c = (slot & 7) * 4;      // sk 0..28
            float4 v = *(const float4*)(Pb + (size_t)(sq0 + r) * Ss + k0 + c);
            Ps[c + 0][r] = v.x; Ps[c + 1][r] = v.y;
            Ps[c + 2][r] = v.z; Ps[c + 3][r] = v.w;
        }
#pragma unroll
        for (int l = 0; l < 2; l++) {
            int slot = tid + l * 256;
            int r = slot >> 4;           // sk 0..31
            int c = (slot & 15) * 4;     // d 0..60
            *(float4*)&Vs[r][c] = *(const float4*)(Vb + (size_t)(k0 + r) * Dd + c);
        }
        __syncthreads();
#pragma unroll
        for (int kk = 0; kk < 32; kk++) {
            float pw[4], vv[4];
            *(float4*)pw = *(const float4*)&Ps[kk][ty * 4];
            *(float4*)vv = *(const float4*)&Vs[kk][tx * 4];
#pragma unroll
            for (int i = 0; i < 4; i++)
#pragma unroll
                for (int j = 0; j < 4; j++) acc[i][j] += pw[i] * vv[j];
        }
        __syncthreads();
    }

#pragma unroll
    for (int i = 0; i < 4; i++) {
        int sq = sq0 + ty * 4 + i;
        float4 o = { acc[i][0], acc[i][1], acc[i][2], acc[i][3] };
        *(float4*)(ctx + (size_t)b * Ss * Dd + (size_t)sq * Dd + h * HDIM + tx * 4) = o;
    }
}

// ---------------------------------------------------------------------------
// Block-wide sum helper (256 threads). Leading sync protects sbuf reuse.
// ---------------------------------------------------------------------------
__device__ __forceinline__ float block_sum(float v, float* sbuf) {
    const int lane = threadIdx.x & 31, w = threadIdx.x >> 5;
#pragma unroll
    for (int o = 16; o > 0; o >>= 1) v += __shfl_xor_sync(~0u, v, o);
    __syncthreads();
    if (lane == 0) sbuf[w] = v;
    __syncthreads();
    float s = 0.f;
#pragma unroll
    for (int i = 0; i < 8; i++) s += sbuf[i];
    return s;
}

// ---------------------------------------------------------------------------
// Fused: t = X + q ; ln1 = LN(t, g1,b1, 1e-8) ; t2 = q + ln1 ;
//        out = LN(t2, g2,b2, 1e-6)
// One block per row (D=1024, 256 threads x 4 cols).
// ---------------------------------------------------------------------------
__global__ void __launch_bounds__(256) ln_a_kernel(
    const float* __restrict__ X, const float* __restrict__ q,
    const float* __restrict__ g1, const float* __restrict__ b1,
    const float* __restrict__ g2, const float* __restrict__ b2,
    float* __restrict__ out)
{
    __shared__ float sbuf[8];
    const size_t row = blockIdx.x;
    const int col = threadIdx.x * 4;
    float4 xv = *(const float4*)(X + row * Dd + col);
    float4 qv = *(const float4*)(q + row * Dd + col);
    float t[4] = { xv.x + qv.x, xv.y + qv.y, xv.z + qv.z, xv.w + qv.w };

    float mu = block_sum(t[0] + t[1] + t[2] + t[3], sbuf) * (1.0f / Dd);
    float ss = 0.f;
#pragma unroll
    for (int i = 0; i < 4; i++) { float d = t[i] - mu; ss += d * d; }
    float var = block_sum(ss, sbuf) * (1.0f / Dd);
    float inv = rsqrtf(var + 1e-8f);

    float4 g = *(const float4*)(g1 + col);
    float4 be = *(const float4*)(b1 + col);
    float qarr[4] = { qv.x, qv.y, qv.z, qv.w };
    float garr[4] = { g.x, g.y, g.z, g.w };
    float barr[4] = { be.x, be.y, be.z, be.w };
    float t2[4];
#pragma unroll
    for (int i = 0; i < 4; i++)
        t2[i] = qarr[i] + (t[i] - mu) * inv * garr[i] + barr[i];

    float mu2 = block_sum(t2[0] + t2[1] + t2[2] + t2[3], sbuf) * (1.0f / Dd);
    float ss2 = 0.f;
#pragma unroll
    for (int i = 0; i < 4; i++) { float d = t2[i] - mu2; ss2 += d * d; }
    float var2 = block_sum(ss2, sbuf) * (1.0f / Dd);
    float inv2 = rsqrtf(var2 + 1e-6f);

    g = *(const float4*)(g2 + col);
    be = *(const float4*)(b2 + col);
    float g2a[4] = { g.x, g.y, g.z, g.w };
    float b2a[4] = { be.x, be.y, be.z, be.w };
    float4 o;
    o.x = (t2[0] - mu2) * inv2 * g2a[0] + b2a[0];
    o.y = (t2[1] - mu2) * inv2 * g2a[1] + b2a[1];
    o.z = (t2[2] - mu2) * inv2 * g2a[2] + b2a[2];
    o.w = (t2[3] - mu2) * inv2 * g2a[3] + b2a[3];
    *(float4*)(out + row * Dd + col) = o;
}

// ---------------------------------------------------------------------------
// Fused: t = Z + res ; out = LN(t, g,b, 1e-6)
// ---------------------------------------------------------------------------
__global__ void __launch_bounds__(256) ln_b_kernel(
    const float* __restrict__ Z, const float* __restrict__ res,
    const float* __restrict__ g1, const float* __restrict__ b1,
    float* __restrict__ out)
{
    __shared__ float sbuf[8];
    const size_t row = blockIdx.x;
    const int col = threadIdx.x * 4;
    float4 zv = *(const float4*)(Z + row * Dd + col);
    float4 rv = *(const float4*)(res + row * Dd + col);
    float t[4] = { zv.x + rv.x, zv.y + rv.y, zv.z + rv.z, zv.w + rv.w };

    float mu = block_sum(t[0] + t[1] + t[2] + t[3], sbuf) * (1.0f / Dd);
    float ss = 0.f;
#pragma unroll
    for (int i = 0; i < 4; i++) { float d = t[i] - mu; ss += d * d; }
    float var = block_sum(ss, sbuf) * (1.0f / Dd);
    float inv = rsqrtf(var + 1e-6f);

    float4 g = *(const float4*)(g1 + col);
    float4 be = *(const float4*)(b1 + col);
    float4 o;
    o.x = (t[0] - mu) * inv * g.x + be.x;
    o.y = (t[1] - mu) * inv * g.y + be.y;
    o.z = (t[2] - mu) * inv * g.z + be.z;
    o.w = (t[3] - mu) * inv * g.w + be.w;
    *(float4*)(out + row * Dd + col) = o;
}

// ---------------------------------------------------------------------------
// kernel_launch
// ---------------------------------------------------------------------------
extern "C" void kernel_launch(void* const* d_in, const int* in_sizes, int n_in,
                              void* d_out, int out_size)
{
    const float* query = (const float*)d_in[0];
    const float* key   = (const float*)d_in[1];
    const float* value = (const float*)d_in[2];
    const float* mask  = (const float*)d_in[3];
    const float* wq = (const float*)d_in[4];
    const float* bq = (const float*)d_in[5];
    const float* wk = (const float*)d_in[6];
    const float* bk = (const float*)d_in[7];
    const float* wv = (const float*)d_in[8];
    const float* bv = (const float*)d_in[9];
    const float* wo = (const float*)d_in[10];
    const float* bo = (const float*)d_in[11];
    const float* ln_mha_g = (const float*)d_in[12];
    const float* ln_mha_b = (const float*)d_in[13];
    const float* w1 = (const float*)d_in[14];
    const float* b1 = (const float*)d_in[15];
    const float* w2 = (const float*)d_in[16];
    const float* b2 = (const float*)d_in[17];
    const float* ln_attn_g = (const float*)d_in[18];
    const float* ln_attn_b = (const float*)d_in[19];
    const float* ln_ffn_g = (const float*)d_in[20];
    const float* ln_ffn_b = (const float*)d_in[21];
    (void)in_sizes; (void)n_in;

    float* out = (float*)d_out;

    float *Qb, *Kb, *Vb, *Fb, *Sb;
    cudaGetSymbolAddress((void**)&Qb, g_Q);
    cudaGetSymbolAddress((void**)&Kb, g_K);
    cudaGetSymbolAddress((void**)&Vb, g_V);
    cudaGetSymbolAddress((void**)&Fb, g_F);
    cudaGetSymbolAddress((void**)&Sb, g_S);

    const long long main_elems = (long long)Mm * Dd;                  // 8,388,608
    const long long attn_elems = (long long)Bb * Hh * Ss * Ss;        // 134,217,728
    float* attn_ext = ((long long)out_size >= main_elems + attn_elems)
                          ? (out + main_elems) : nullptr;

    dim3 blk(256);

    // QKV projections
    sgemm_bias<<<dim3(Dd / 128, Mm / 128), blk>>>(query, wq, bq, Qb, Mm, Dd, Dd, 0);
    sgemm_bias<<<dim3(Dd / 128, Mm / 128), blk>>>(key,   wk, bk, Kb, Mm, Dd, Dd, 0);
    sgemm_bias<<<dim3(Dd / 128, Mm / 128), blk>>>(value, wv, bv, Vb, Mm, Dd, Dd, 0);

    // Attention scores + softmax (in place, mirrored to attn_weights output)
    scores_kernel<<<dim3(Ss / 64, Ss / 64, Bb * Hh), blk>>>(Qb, Kb, mask, Sb);
    softmax_kernel<<<Bb * Hh * Ss, blk>>>(Sb, attn_ext);

    // context = P @ V  (into g_Q; Q projections no longer needed)
    pv_kernel<<<dim3(Ss / 64, Bb * Hh), blk>>>(Sb, Vb, Qb);

    // O-projection (into g_K; K projections no longer needed)
    sgemm_bias<<<dim3(Dd / 128, Mm / 128), blk>>>(Qb, wo, bo, Kb, Mm, Dd, Dd, 0);

    // Double LayerNorm with residuals (attn_out into g_V; V no longer needed)
    ln_a_kernel<<<Mm, blk>>>(Kb, query, ln_mha_g, ln_mha_b, ln_attn_g, ln_attn_b, Vb);

    // FFN
    sgemm_bias<<<dim3(Ff / 128, Mm / 128), blk>>>(Vb, w1, b1, Fb, Mm, Ff, Dd, 1);
    sgemm_bias<<<dim3(Dd / 128, Mm / 128), blk>>>(Fb, w2, b2, Kb, Mm, Dd, Ff, 0);

    // Final LayerNorm -> main output
    ln_b_kernel<<<Mm, blk>>>(Kb, Vb, ln_ffn_g, ln_ffn_b, out);
}

// round 3
// speedup vs baseline: 2.3811x; 2.3811x over previous
#include <cuda_runtime.h>
#include <cuda_fp16.h>
#include <math.h>
#include <stdint.h>

#define Bb 8
#define Ss 1024
#define Dd 1024
#define Hh 16
#define HDIM 64
#define Ff 4096
#define Mm (Bb*Ss)

// ---------------------------------------------------------------------------
// Scratch (device globals)
// ---------------------------------------------------------------------------
__device__ float g_Q[(size_t)Mm * Dd];
__device__ float g_K[(size_t)Mm * Dd];
__device__ float g_V[(size_t)Mm * Dd];
__device__ float g_F[(size_t)Mm * Ff];
__device__ float g_S[(size_t)Bb * Hh * Ss * Ss];
__device__ float g_WT[(size_t)(4 * Dd * Dd + Dd * Ff + Ff * Dd)];
__device__ float g_Vt[(size_t)Bb * Hh * HDIM * Ss];

// ---------------------------------------------------------------------------
// Warp MMA helpers (baseline PTX: sm_80+, works on sm_103 non-'a' target)
// ---------------------------------------------------------------------------
__device__ __forceinline__ uint32_t smem_u32(const void* p) {
    uint32_t a;
    asm("{ .reg .u64 t; cvta.to.shared.u64 t, %1; cvt.u32.u64 %0, t; }"
        : "=r"(a) : "l"(p));
    return a;
}
__device__ __forceinline__ void ldsm4(uint32_t& r0, uint32_t& r1, uint32_t& r2,
                                      uint32_t& r3, uint32_t addr) {
    asm volatile("ldmatrix.sync.aligned.m8n8.x4.shared.b16 {%0,%1,%2,%3}, [%4];"
                 : "=r"(r0), "=r"(r1), "=r"(r2), "=r"(r3) : "r"(addr));
}
__device__ __forceinline__ void mma16816(float* d, const uint32_t* a,
                                         const uint32_t* b) {
    asm volatile(
        "mma.sync.aligned.m16n8k16.row.col.f32.f16.f16.f32 "
        "{%0,%1,%2,%3}, {%4,%5,%6,%7}, {%8,%9}, {%0,%1,%2,%3};"
        : "+f"(d[0]), "+f"(d[1]), "+f"(d[2]), "+f"(d[3])
        : "r"(a[0]), "r"(a[1]), "r"(a[2]), "r"(a[3]), "r"(b[0]), "r"(b[1]));
}
// Split fp32x4 into fp16 hi/lo pairs and store (two 4B stores each)
__device__ __forceinline__ void split_store(char* ph, char* pl, int off, float4 v) {
    __half2 h0 = __floats2half2_rn(v.x, v.y);
    __half2 h1 = __floats2half2_rn(v.z, v.w);
    float2 f0 = __half22float2(h0), f1 = __half22float2(h1);
    __half2 l0 = __floats2half2_rn(v.x - f0.x, v.y - f0.y);
    __half2 l1 = __floats2half2_rn(v.z - f1.x, v.w - f1.y);
    *(__half2*)(ph + off) = h0; *(__half2*)(ph + off + 4) = h1;
    *(__half2*)(pl + off) = l0; *(__half2*)(pl + off + 4) = l1;
}

// ---------------------------------------------------------------------------
// GEMM via mma.sync fp16 with hi/lo split (fp32-equivalent accuracy):
//   C[128 x BN] tile = A[128,K] (K-major) @ B[BN,K]^T (K-major rows)
//   D = Ah*Bh + Al*Bh + Ah*Bl  (fp32 accum)
//   Batch over blockIdx.z: offset = (z>>4)*s1 + (z&15)*s2 per tensor.
//   EPI: 0=+bias  1=+bias,relu  2=scores(x/8+(1-mask)*-1e4)  3=plain
// ---------------------------------------------------------------------------
template<int BN, int EPI>
__global__ void __launch_bounds__(256, 1) gemm_hmma(
    const float* __restrict__ A, long long lda, long long a1, long long a2,
    const float* __restrict__ B, long long ldb, long long b1, long long b2,
    float* __restrict__ C, long long ldc, long long c1, long long c2,
    const float* __restrict__ aux, int K)
{
    constexpr int MF = 4;            // m16 frags per warp (warp m span 64)
    constexpr int NF = BN / 32;      // n8 frags per warp (warp n span BN/4)
    constexpr int NB4 = BN / 32;     // B float4 loads per thread per chunk
    constexpr int STAGE = 20480 + BN * 160;  // bytes per double-buffer stage

    extern __shared__ char dsm[];

    const int tid = threadIdx.x, lane = tid & 31, wid = tid >> 5;
    const int zb = blockIdx.z >> 4, zh = blockIdx.z & 15;
    const int row0 = blockIdx.y * 128, col0 = blockIdx.x * BN;
    const int m0w = (wid >> 2) * 64, n0w = (wid & 3) * (BN / 4);

    const float* Ab = A + zb * a1 + zh * a2 + (size_t)row0 * lda;
    const float* Bp = B + zb * b1 + zh * b2 + (size_t)col0 * ldb;
    float* Cb = C + zb * c1 + zh * c2;

    float acc[MF][NF][4];
#pragma unroll
    for (int i = 0; i < MF; i++)
#pragma unroll
        for (int j = 0; j < NF; j++)
#pragma unroll
            for (int k = 0; k < 4; k++) acc[i][j][k] = 0.f;

    const uint32_t sbase = smem_u32(dsm);

    float4 ra[4], rb[NB4];
    // ---- prologue: load + stage chunk 0 ----
#pragma unroll
    for (int i = 0; i < 4; i++) {
        int slot = tid + i * 256;
        ra[i] = *(const float4*)(Ab + (size_t)(slot >> 3) * lda + (slot & 7) * 4);
    }
#pragma unroll
    for (int i = 0; i < NB4; i++) {
        int slot = tid + i * 256;
        rb[i] = *(const float4*)(Bp + (size_t)(slot >> 3) * ldb + (slot & 7) * 4);
    }
    {
        char* Ah = dsm;            char* Al = Ah + 10240;
        char* Bh = dsm + 20480;    char* Bl = Bh + BN * 80;
#pragma unroll
        for (int i = 0; i < 4; i++) {
            int slot = tid + i * 256;
            split_store(Ah, Al, (slot >> 3) * 80 + (slot & 7) * 8, ra[i]);
        }
#pragma unroll
        for (int i = 0; i < NB4; i++) {
            int slot = tid + i * 256;
            split_store(Bh, Bl, (slot >> 3) * 80 + (slot & 7) * 8, rb[i]);
        }
    }
    __syncthreads();

    const int NC = K >> 5;
    for (int c = 0; c < NC; c++) {
        const int s = c & 1;
        if (c + 1 < NC) {
            const int k0 = (c + 1) << 5;
#pragma unroll
            for (int i = 0; i < 4; i++) {
                int slot = tid + i * 256;
                ra[i] = *(const float4*)(Ab + (size_t)(slot >> 3) * lda + k0 + (slot & 7) * 4);
            }
#pragma unroll
            for (int i = 0; i < NB4; i++) {
                int slot = tid + i * 256;
                rb[i] = *(const float4*)(Bp + (size_t)(slot >> 3) * ldb + k0 + (slot & 7) * 4);
            }
        }
        // ---- compute on stage s ----
        const uint32_t aAh = sbase + s * STAGE;
        const uint32_t aAl = aAh + 10240;
        const uint32_t aBh = aAh + 20480;
        const uint32_t aBl = aBh + BN * 80;
#pragma unroll
        for (int kk = 0; kk < 32; kk += 16) {
            uint32_t ah[MF][4], al[MF][4], bh[NF][2], bl[NF][2];
#pragma unroll
            for (int mi = 0; mi < MF; mi++) {
                uint32_t ao = (uint32_t)((m0w + mi * 16 + (lane & 15)) * 40 +
                                         kk + ((lane >> 4) << 3)) * 2;
                ldsm4(ah[mi][0], ah[mi][1], ah[mi][2], ah[mi][3], aAh + ao);
                ldsm4(al[mi][0], al[mi][1], al[mi][2], al[mi][3], aAl + ao);
            }
#pragma unroll
            for (int np = 0; np < NF / 2; np++) {
                uint32_t bo = (uint32_t)((n0w + np * 16 + ((lane >> 4) << 3) +
                                          (lane & 7)) * 40 +
                                         kk + ((lane >> 3) & 1) * 8) * 2;
                ldsm4(bh[2 * np][0], bh[2 * np][1], bh[2 * np + 1][0],
                      bh[2 * np + 1][1], aBh + bo);
                ldsm4(bl[2 * np][0], bl[2 * np][1], bl[2 * np + 1][0],
                      bl[2 * np + 1][1], aBl + bo);
            }
#pragma unroll
            for (int mi = 0; mi < MF; mi++)
#pragma unroll
                for (int ni = 0; ni < NF; ni++) {
                    mma16816(acc[mi][ni], ah[mi], bh[ni]);
                    mma16816(acc[mi][ni], al[mi], bh[ni]);
                    mma16816(acc[mi][ni], ah[mi], bl[ni]);
                }
        }
        if (c + 1 < NC) {
            char* Ah = dsm + (s ^ 1) * STAGE;  char* Al = Ah + 10240;
            char* Bh = Ah + 20480;             char* Bl = Bh + BN * 80;
#pragma unroll
            for (int i = 0; i < 4; i++) {
                int slot = tid + i * 256;
                split_store(Ah, Al, (slot >> 3) * 80 + (slot & 7) * 8, ra[i]);
            }
#pragma unroll
            for (int i = 0; i < NB4; i++) {
                int slot = tid + i * 256;
                split_store(Bh, Bl, (slot >> 3) * 80 + (slot & 7) * 8, rb[i]);
            }
        }
        __syncthreads();
    }

    // ---- epilogue: fragment-direct stores ----
#pragma unroll
    for (int ni = 0; ni < NF; ni++) {
        const int col = col0 + n0w + ni * 8 + (lane & 3) * 2;
        float2 e = make_float2(0.f, 0.f);
        if (EPI == 0 || EPI == 1) {
            e = *(const float2*)(aux + col);
        } else if (EPI == 2) {
            float2 m = *(const float2*)(aux + (size_t)zb * Ss + col);
            e.x = (1.f - m.x) * -10000.f;
            e.y = (1.f - m.y) * -10000.f;
        }
#pragma unroll
        for (int mi = 0; mi < MF; mi++) {
            const int r0g = row0 + m0w + mi * 16 + (lane >> 2);
            float* a = acc[mi][ni];
            float2 v0, v1;
            if (EPI == 2) {
                v0 = make_float2(a[0] * 0.125f + e.x, a[1] * 0.125f + e.y);
                v1 = make_float2(a[2] * 0.125f + e.x, a[3] * 0.125f + e.y);
            } else {
                v0 = make_float2(a[0] + e.x, a[1] + e.y);
                v1 = make_float2(a[2] + e.x, a[3] + e.y);
                if (EPI == 1) {
                    v0.x = fmaxf(v0.x, 0.f); v0.y = fmaxf(v0.y, 0.f);
                    v1.x = fmaxf(v1.x, 0.f); v1.y = fmaxf(v1.y, 0.f);
                }
            }
            *(float2*)(Cb + (size_t)r0g * ldc + col) = v0;
            *(float2*)(Cb + (size_t)(r0g + 8) * ldc + col) = v1;
        }
    }
}

// ---------------------------------------------------------------------------
// Weight transpose: WT[c][r] = W[r][c]
// ---------------------------------------------------------------------------
__global__ void transpose_f32(const float* __restrict__ W, float* __restrict__ WT,
                              int R, int C)
{
    __shared__ float t[32][33];
    int c0 = blockIdx.x * 32, r0 = blockIdx.y * 32;
#pragma unroll
    for (int i = threadIdx.y; i < 32; i += 8)
        t[i][threadIdx.x] = W[(size_t)(r0 + i) * C + c0 + threadIdx.x];
    __syncthreads();
#pragma unroll
    for (int i = threadIdx.y; i < 32; i += 8)
        WT[(size_t)(c0 + i) * R + r0 + threadIdx.x] = t[threadIdx.x][i];
}

// V^T per (b,h): Vt[bh][d][sk] = V[b][sk][h*64+d]
__global__ void vt_kernel(const float* __restrict__ V, float* __restrict__ Vt)
{
    __shared__ float t[32][33];
    const int bh = blockIdx.z, b = bh >> 4, h = bh & 15;
    const int sk0 = blockIdx.x * 32, d0 = blockIdx.y * 32;
    const float* Vb = V + (size_t)b * Ss * Dd + h * HDIM;
#pragma unroll
    for (int i = threadIdx.y; i < 32; i += 8)
        t[i][threadIdx.x] = Vb[(size_t)(sk0 + i) * Dd + d0 + threadIdx.x];
    __syncthreads();
    float* Vtb = Vt + (size_t)bh * HDIM * Ss;
#pragma unroll
    for (int i = threadIdx.y; i < 32; i += 8)
        Vtb[(size_t)(d0 + i) * Ss + sk0 + threadIdx.x] = t[threadIdx.x][i];
}

// ---------------------------------------------------------------------------
// Softmax (row of 1024), in place + mirror to attn_weights output
// ---------------------------------------------------------------------------
__global__ void __launch_bounds__(256) softmax_kernel(
    float* __restrict__ Sbuf, float* __restrict__ ext)
{
    __shared__ float sbuf[8];
    const size_t row = blockIdx.x;
    float* p = Sbuf + row * Ss;
    const int tid = threadIdx.x;
    const int lane = tid & 31, w = tid >> 5;

    float4 x = *(const float4*)(p + tid * 4);
    float m = fmaxf(fmaxf(x.x, x.y), fmaxf(x.z, x.w));
#pragma unroll
    for (int o = 16; o > 0; o >>= 1) m = fmaxf(m, __shfl_xor_sync(~0u, m, o));
    if (lane == 0) sbuf[w] = m;
    __syncthreads();
    m = sbuf[0];
#pragma unroll
    for (int i = 1; i < 8; i++) m = fmaxf(m, sbuf[i]);

    float4 e;
    e.x = expf(x.x - m); e.y = expf(x.y - m);
    e.z = expf(x.z - m); e.w = expf(x.w - m);
    float s = e.x + e.y + e.z + e.w;
#pragma unroll
    for (int o = 16; o > 0; o >>= 1) s += __shfl_xor_sync(~0u, s, o);
    __syncthreads();
    if (lane == 0) sbuf[w] = s;
    __syncthreads();
    s = 0.f;
#pragma unroll
    for (int i = 0; i < 8; i++) s += sbuf[i];
    float inv = 1.0f / s;
    e.x *= inv; e.y *= inv; e.z *= inv; e.w *= inv;
    *(float4*)(p + tid * 4) = e;
    if (ext) *(float4*)(ext + row * Ss + tid * 4) = e;
}

// ---------------------------------------------------------------------------
// LayerNorm kernels (fused residuals)
// ---------------------------------------------------------------------------
__device__ __forceinline__ float block_sum(float v, float* sbuf) {
    const int lane = threadIdx.x & 31, w = threadIdx.x >> 5;
#pragma unroll
    for (int o = 16; o > 0; o >>= 1) v += __shfl_xor_sync(~0u, v, o);
    __syncthreads();
    if (lane == 0) sbuf[w] = v;
    __syncthreads();
    float s = 0.f;
#pragma unroll
    for (int i = 0; i < 8; i++) s += sbuf[i];
    return s;
}

__global__ void __launch_bounds__(256) ln_a_kernel(
    const float* __restrict__ X, const float* __restrict__ q,
    const float* __restrict__ g1, const float* __restrict__ b1,
    const float* __restrict__ g2, const float* __restrict__ b2,
    float* __restrict__ out)
{
    __shared__ float sbuf[8];
    const size_t row = blockIdx.x;
    const int col = threadIdx.x * 4;
    float4 xv = *(const float4*)(X + row * Dd + col);
    float4 qv = *(const float4*)(q + row * Dd + col);
    float t[4] = { xv.x + qv.x, xv.y + qv.y, xv.z + qv.z, xv.w + qv.w };

    float mu = block_sum(t[0] + t[1] + t[2] + t[3], sbuf) * (1.0f / Dd);
    float ss = 0.f;
#pragma unroll
    for (int i = 0; i < 4; i++) { float d = t[i] - mu; ss += d * d; }
    float var = block_sum(ss, sbuf) * (1.0f / Dd);
    float inv = rsqrtf(var + 1e-8f);

    float4 g = *(const float4*)(g1 + col);
    float4 be = *(const float4*)(b1 + col);
    float qarr[4] = { qv.x, qv.y, qv.z, qv.w };
    float garr[4] = { g.x, g.y, g.z, g.w };
    float barr[4] = { be.x, be.y, be.z, be.w };
    float t2[4];
#pragma unroll
    for (int i = 0; i < 4; i++)
        t2[i] = qarr[i] + (t[i] - mu) * inv * garr[i] + barr[i];

    float mu2 = block_sum(t2[0] + t2[1] + t2[2] + t2[3], sbuf) * (1.0f / Dd);
    float ss2 = 0.f;
#pragma unroll
    for (int i = 0; i < 4; i++) { float d = t2[i] - mu2; ss2 += d * d; }
    float var2 = block_sum(ss2, sbuf) * (1.0f / Dd);
    float inv2 = rsqrtf(var2 + 1e-6f);

    g = *(const float4*)(g2 + col);
    be = *(const float4*)(b2 + col);
    float g2a[4] = { g.x, g.y, g.z, g.w };
    float b2a[4] = { be.x, be.y, be.z, be.w };
    float4 o;
    o.x = (t2[0] - mu2) * inv2 * g2a[0] + b2a[0];
    o.y = (t2[1] - mu2) * inv2 * g2a[1] + b2a[1];
    o.z = (t2[2] - mu2) * inv2 * g2a[2] + b2a[2];
    o.w = (t2[3] - mu2) * inv2 * g2a[3] + b2a[3];
    *(float4*)(out + row * Dd + col) = o;
}

__global__ void __launch_bounds__(256) ln_b_kernel(
    const float* __restrict__ Z, const float* __restrict__ res,
    const float* __restrict__ g1, const float* __restrict__ b1,
    float* __restrict__ out)
{
    __shared__ float sbuf[8];
    const size_t row = blockIdx.x;
    const int col = threadIdx.x * 4;
    float4 zv = *(const float4*)(Z + row * Dd + col);
    float4 rv = *(const float4*)(res + row * Dd + col);
    float t[4] = { zv.x + rv.x, zv.y + rv.y, zv.z + rv.z, zv.w + rv.w };

    float mu = block_sum(t[0] + t[1] + t[2] + t[3], sbuf) * (1.0f / Dd);
    float ss = 0.f;
#pragma unroll
    for (int i = 0; i < 4; i++) { float d = t[i] - mu; ss += d * d; }
    float var = block_sum(ss, sbuf) * (1.0f / Dd);
    float inv = rsqrtf(var + 1e-6f);

    float4 g = *(const float4*)(g1 + col);
    float4 be = *(const float4*)(b1 + col);
    float4 o;
    o.x = (t[0] - mu) * inv * g.x + be.x;
    o.y = (t[1] - mu) * inv * g.y + be.y;
    o.z = (t[2] - mu) * inv * g.z + be.z;
    o.w = (t[3] - mu) * inv * g.w + be.w;
    *(float4*)(out + row * Dd + col) = o;
}

// ---------------------------------------------------------------------------
// kernel_launch
// ---------------------------------------------------------------------------
extern "C" void kernel_launch(void* const* d_in, const int* in_sizes, int n_in,
                              void* d_out, int out_size)
{
    const float* query = (const float*)d_in[0];
    const float* key   = (const float*)d_in[1];
    const float* value = (const float*)d_in[2];
    const float* mask  = (const float*)d_in[3];
    const float* wq = (const float*)d_in[4];
    const float* bq = (const float*)d_in[5];
    const float* wk = (const float*)d_in[6];
    const float* bk = (const float*)d_in[7];
    const float* wv = (const float*)d_in[8];
    const float* bv = (const float*)d_in[9];
    const float* wo = (const float*)d_in[10];
    const float* bo = (const float*)d_in[11];
    const float* ln_mha_g = (const float*)d_in[12];
    const float* ln_mha_b = (const float*)d_in[13];
    const float* w1 = (const float*)d_in[14];
    const float* b1 = (const float*)d_in[15];
    const float* w2 = (const float*)d_in[16];
    const float* b2 = (const float*)d_in[17];
    const float* ln_attn_g = (const float*)d_in[18];
    const float* ln_attn_b = (const float*)d_in[19];
    const float* ln_ffn_g = (const float*)d_in[20];
    const float* ln_ffn_b = (const float*)d_in[21];
    (void)in_sizes; (void)n_in;

    float* out = (float*)d_out;

    float *Qb, *Kb, *Vb, *Fb, *Sb, *WT, *Vt;
    cudaGetSymbolAddress((void**)&Qb, g_Q);
    cudaGetSymbolAddress((void**)&Kb, g_K);
    cudaGetSymbolAddress((void**)&Vb, g_V);
    cudaGetSymbolAddress((void**)&Fb, g_F);
    cudaGetSymbolAddress((void**)&Sb, g_S);
    cudaGetSymbolAddress((void**)&WT, g_WT);
    cudaGetSymbolAddress((void**)&Vt, g_Vt);

    float* wqT = WT;
    float* wkT = WT + (size_t)Dd * Dd;
    float* wvT = WT + (size_t)2 * Dd * Dd;
    float* woT = WT + (size_t)3 * Dd * Dd;
    float* w1T = WT + (size_t)4 * Dd * Dd;
    float* w2T = WT + (size_t)4 * Dd * Dd + (size_t)Dd * Ff;

    const long long main_elems = (long long)Mm * Dd;
    const long long attn_elems = (long long)Bb * Hh * Ss * Ss;
    float* attn_ext = ((long long)out_size >= main_elems + attn_elems)
                          ? (out + main_elems) : nullptr;

    const int DSZ128 = 2 * (20480 + 128 * 160);   // 81920
    const int DSZ64  = 2 * (20480 + 64 * 160);    // 61440
    cudaFuncSetAttribute(gemm_hmma<128, 0>, cudaFuncAttributeMaxDynamicSharedMemorySize, DSZ128);
    cudaFuncSetAttribute(gemm_hmma<128, 1>, cudaFuncAttributeMaxDynamicSharedMemorySize, DSZ128);
    cudaFuncSetAttribute(gemm_hmma<128, 2>, cudaFuncAttributeMaxDynamicSharedMemorySize, DSZ128);
    cudaFuncSetAttribute(gemm_hmma<64, 3>,  cudaFuncAttributeMaxDynamicSharedMemorySize, DSZ64);

    dim3 tblk(32, 8);
    transpose_f32<<<dim3(Dd / 32, Dd / 32), tblk>>>(wq, wqT, Dd, Dd);
    transpose_f32<<<dim3(Dd / 32, Dd / 32), tblk>>>(wk, wkT, Dd, Dd);
    transpose_f32<<<dim3(Dd / 32, Dd / 32), tblk>>>(wv, wvT, Dd, Dd);
    transpose_f32<<<dim3(Dd / 32, Dd / 32), tblk>>>(wo, woT, Dd, Dd);
    transpose_f32<<<dim3(Ff / 32, Dd / 32), tblk>>>(w1, w1T, Dd, Ff);
    transpose_f32<<<dim3(Dd / 32, Ff / 32), tblk>>>(w2, w2T, Ff, Dd);

    // QKV projections
    gemm_hmma<128, 0><<<dim3(Dd / 128, Mm / 128, 1), 256, DSZ128>>>(
        query, Dd, 0, 0, wqT, Dd, 0, 0, Qb, Dd, 0, 0, bq, Dd);
    gemm_hmma<128, 0><<<dim3(Dd / 128, Mm / 128, 1), 256, DSZ128>>>(
        key, Dd, 0, 0, wkT, Dd, 0, 0, Kb, Dd, 0, 0, bk, Dd);
    gemm_hmma<128, 0><<<dim3(Dd / 128, Mm / 128, 1), 256, DSZ128>>>(
        value, Dd, 0, 0, wvT, Dd, 0, 0, Vb, Dd, 0, 0, bv, Dd);

    // V^T per head
    vt_kernel<<<dim3(Ss / 32, HDIM / 32, Bb * Hh), tblk>>>(Vb, Vt);

    // scores = QK^T/8 + mask
    gemm_hmma<128, 2><<<dim3(Ss / 128, Ss / 128, Bb * Hh), 256, DSZ128>>>(
        Qb, Dd, (long long)Ss * Dd, HDIM,
        Kb, Dd, (long long)Ss * Dd, HDIM,
        Sb, Ss, 16LL * Ss * Ss, (long long)Ss * Ss,
        mask, HDIM);

    // softmax (in place; mirror to attn_weights output)
    softmax_kernel<<<Bb * Hh * Ss, 256>>>(Sb, attn_ext);

    // context = P @ V  (into g_Q)
    gemm_hmma<64, 3><<<dim3(1, Ss / 128, Bb * Hh), 256, DSZ64>>>(
        Sb, Ss, 16LL * Ss * Ss, (long long)Ss * Ss,
        Vt, Ss, 16LL * HDIM * Ss, (long long)HDIM * Ss,
        Qb, Dd, (long long)Ss * Dd, HDIM,
        nullptr, Ss);

    // O-projection (into g_K)
    gemm_hmma<128, 0><<<dim3(Dd / 128, Mm / 128, 1), 256, DSZ128>>>(
        Qb, Dd, 0, 0, woT, Dd, 0, 0, Kb, Dd, 0, 0, bo, Dd);

    // Double LayerNorm with residuals -> attn_out in g_V
    ln_a_kernel<<<Mm, 256>>>(Kb, query, ln_mha_g, ln_mha_b, ln_attn_g, ln_attn_b, Vb);

    // FFN
    gemm_hmma<128, 1><<<dim3(Ff / 128, Mm / 128, 1), 256, DSZ128>>>(
        Vb, Dd, 0, 0, w1T, Dd, 0, 0, Fb, Ff, 0, 0, b1, Dd);
    gemm_hmma<128, 0><<<dim3(Dd / 128, Mm / 128, 1), 256, DSZ128>>>(
        Fb, Ff, 0, 0, w2T, Ff, 0, 0, Kb, Dd, 0, 0, b2, Ff);

    // Final LayerNorm -> main output
    ln_b_kernel<<<Mm, 256>>>(Kb, Vb, ln_ffn_g, ln_ffn_b, out);
}